// round 1
// baseline (speedup 1.0000x reference)
#include <cuda_runtime.h>
#include <cuda_bf16.h>
#include <math.h>

// Problem constants
#define Bsz 2
#define Tn 2048
#define Dm 2048
#define NHq 16
#define NKV 8
#define HD 128
#define MROWS (Bsz * Tn)          // 4096 tokens
#define QKVN 4096                 // 2048 q | 1024 k | 1024 v
#define KOFF 2048
#define VOFF 3072
#define ENCN (NHq * HD)           // 2048
#define BIG_NEG -2.3819763e38f

// Scratch (device globals: allocation-free per harness rules)
__device__ float g_wc[Dm * QKVN];      // packed QKV weights [K=2048][N=4096]
__device__ float g_qkv[(size_t)MROWS * QKVN];   // projections, rope'd in place
__device__ float g_enc[(size_t)MROWS * ENCN];   // attention output

// ---------------------------------------------------------------------------
// Pack w_q [16,2048,128] and w_kv [2,8,2048,128] into K-major [2048][4096]
// ---------------------------------------------------------------------------
__global__ void pack_w_kernel(const float* __restrict__ wq,
                              const float* __restrict__ wkv) {
    int idx = blockIdx.x * blockDim.x + threadIdx.x;
    if (idx >= Dm * QKVN) return;
    int j = idx & (QKVN - 1);
    int d = idx >> 12;
    float v;
    if (j < KOFF) {
        int n = j >> 7, h = j & 127;
        v = wq[((size_t)n * Dm + d) * HD + h];
    } else if (j < VOFF) {
        int jj = j - KOFF;
        int n = jj >> 7, h = jj & 127;
        v = wkv[((size_t)n * Dm + d) * HD + h];
    } else {
        int jj = j - VOFF;
        int n = jj >> 7, h = jj & 127;
        v = wkv[((size_t)(NKV + n) * Dm + d) * HD + h];
    }
    g_wc[idx] = v;
}

// ---------------------------------------------------------------------------
// SGEMM: C[M,N] = A[M,K] * B[K,N], all row-major, dims multiples of tile
// 128x128 block tile, BK=16, 256 threads, 8x8 per thread
// ---------------------------------------------------------------------------
__global__ __launch_bounds__(256) void sgemm_kernel(
    const float* __restrict__ A, const float* __restrict__ B,
    float* __restrict__ C, int M, int N, int K) {
    const int BK = 16;
    __shared__ float As[BK][128];
    __shared__ float Bs[BK][128];
    int tid = threadIdx.x;
    int tx = tid & 15, ty = tid >> 4;
    int rowBlock = blockIdx.y * 128, colBlock = blockIdx.x * 128;

    float acc[8][8];
#pragma unroll
    for (int i = 0; i < 8; i++)
#pragma unroll
        for (int j = 0; j < 8; j++) acc[i][j] = 0.f;

    int aRow = tid >> 2;
    int aCol = (tid & 3) << 2;
    int bRow = tid >> 5;
    int bCol = (tid & 31) << 2;
    const float* Aptr = A + (size_t)rowBlock * K;

    for (int k0 = 0; k0 < K; k0 += BK) {
#pragma unroll
        for (int i = 0; i < 2; i++) {
            int r = aRow + i * 64;
            float4 v = *(const float4*)(Aptr + (size_t)r * K + k0 + aCol);
            As[aCol + 0][r] = v.x;
            As[aCol + 1][r] = v.y;
            As[aCol + 2][r] = v.z;
            As[aCol + 3][r] = v.w;
        }
#pragma unroll
        for (int i = 0; i < 2; i++) {
            int r = bRow + i * 8;
            *(float4*)&Bs[r][bCol] =
                *(const float4*)(B + (size_t)(k0 + r) * N + colBlock + bCol);
        }
        __syncthreads();
#pragma unroll
        for (int kk = 0; kk < BK; kk++) {
            float a[8], bb[8];
            *(float4*)&a[0] = *(float4*)&As[kk][ty * 8];
            *(float4*)&a[4] = *(float4*)&As[kk][ty * 8 + 4];
            *(float4*)&bb[0] = *(float4*)&Bs[kk][tx * 8];
            *(float4*)&bb[4] = *(float4*)&Bs[kk][tx * 8 + 4];
#pragma unroll
            for (int i = 0; i < 8; i++)
#pragma unroll
                for (int j = 0; j < 8; j++) acc[i][j] += a[i] * bb[j];
        }
        __syncthreads();
    }

#pragma unroll
    for (int i = 0; i < 8; i++) {
        float* crow = C + (size_t)(rowBlock + ty * 8 + i) * N + colBlock + tx * 8;
        float4 o1 = {acc[i][0], acc[i][1], acc[i][2], acc[i][3]};
        float4 o2 = {acc[i][4], acc[i][5], acc[i][6], acc[i][7]};
        *(float4*)crow = o1;
        *(float4*)(crow + 4) = o2;
    }
}

// ---------------------------------------------------------------------------
// RoPE in-place on q (with 1/sqrt(HD) scale) and k inside g_qkv.
// Mimics the reference's fp32 powf / division / sincos sequence.
// ---------------------------------------------------------------------------
__global__ void rope_kernel(const int* __restrict__ positions) {
    int idx = blockIdx.x * blockDim.x + threadIdx.x;
    const int total = MROWS * (NHq + NKV) * 64;
    if (idx >= total) return;
    int p = idx & 63;
    int rest = idx >> 6;
    int head = rest % (NHq + NKV);
    int m = rest / (NHq + NKV);
    float t = (float)positions[m];
    float frac = (float)(2 * p) * (1.0f / 128.0f);
    float timescale = powf(10000.0f, frac);
    float ang = t / timescale;
    float s, c;
    sincosf(ang, &s, &c);
    int col = (head < NHq) ? head * HD : KOFF + (head - NHq) * HD;
    float scale = (head < NHq) ? 0.08838834764831845f : 1.0f;  // 128^-0.5
    float* base = g_qkv + (size_t)m * QKVN + col;
    float x1 = base[p], x2 = base[p + 64];
    base[p] = (x1 * c - x2 * s) * scale;
    base[p + 64] = (x2 * c + x1 * s) * scale;
}

// ---------------------------------------------------------------------------
// Flash attention: block = (q-tile 64 rows, head, batch); 256 threads.
// S = softcap(Q K^T), causal, online softmax, O += P V.
// K and V share one smem buffer (V loaded after S is materialized).
// ---------------------------------------------------------------------------
#define SQS 132  // padded row stride for Q/K/V tiles (bank-conflict relief)

__global__ __launch_bounds__(256) void attn_kernel() {
    extern __shared__ float sm[];
    float* Qs = sm;                      // 64*132
    float* KVs = Qs + 64 * SQS;          // 64*132
    float* Ss = KVs + 64 * SQS;          // 64*65
    float* rowM = Ss + 64 * 65;
    float* rowL = rowM + 64;
    float* rowScale = rowL + 64;

    int tq = blockIdx.x;   // 32 q tiles
    int n = blockIdx.y;    // 16 heads
    int b = blockIdx.z;    // 2 batch
    int kvh = n >> 1;      // G = 2
    int tid = threadIdx.x;
    int tx = tid & 15, ty = tid >> 4;
    int rowBase = b * Tn + tq * 64;

    // Load Q tile
    for (int i = tid; i < 64 * 32; i += 256) {
        int r = i >> 5, c4 = (i & 31) << 2;
        *(float4*)&Qs[r * SQS + c4] =
            *(const float4*)&g_qkv[(size_t)(rowBase + r) * QKVN + n * HD + c4];
    }
    if (tid < 64) { rowM[tid] = -3.4e38f; rowL[tid] = 0.f; }

    float acc[4][8];
#pragma unroll
    for (int i = 0; i < 4; i++)
#pragma unroll
        for (int j = 0; j < 8; j++) acc[i][j] = 0.f;
    __syncthreads();

    for (int ts = 0; ts <= tq; ts++) {
        // Load K tile
        for (int i = tid; i < 64 * 32; i += 256) {
            int r = i >> 5, c4 = (i & 31) << 2;
            *(float4*)&KVs[r * SQS + c4] = *(const float4*)
                &g_qkv[(size_t)(b * Tn + ts * 64 + r) * QKVN + KOFF + kvh * HD + c4];
        }
        __syncthreads();

        // S = Q K^T : thread computes 4x4 of the 64x64 tile
        float s4[4][4];
#pragma unroll
        for (int i = 0; i < 4; i++)
#pragma unroll
            for (int j = 0; j < 4; j++) s4[i][j] = 0.f;
#pragma unroll 2
        for (int h = 0; h < HD; h += 4) {
            float4 qv[4], kv[4];
#pragma unroll
            for (int i = 0; i < 4; i++)
                qv[i] = *(float4*)&Qs[(ty * 4 + i) * SQS + h];
#pragma unroll
            for (int j = 0; j < 4; j++)
                kv[j] = *(float4*)&KVs[(tx * 4 + j) * SQS + h];
#pragma unroll
            for (int i = 0; i < 4; i++)
#pragma unroll
                for (int j = 0; j < 4; j++)
                    s4[i][j] += qv[i].x * kv[j].x + qv[i].y * kv[j].y +
                                qv[i].z * kv[j].z + qv[i].w * kv[j].w;
        }

        // Softcap, causal mask, store to smem
#pragma unroll
        for (int i = 0; i < 4; i++) {
            int gr = tq * 64 + ty * 4 + i;
#pragma unroll
            for (int j = 0; j < 4; j++) {
                int gc = ts * 64 + tx * 4 + j;
                float v = tanhf(s4[i][j] * 0.02f) * 50.0f;
                if (gc > gr) v = BIG_NEG;
                Ss[(ty * 4 + i) * 65 + tx * 4 + j] = v;
            }
        }
        __syncthreads();

        // Online softmax (one thread per row)
        if (tid < 64) {
            float mOld = rowM[tid];
            float m = mOld;
            float* srow = Ss + tid * 65;
#pragma unroll 8
            for (int c = 0; c < 64; c++) m = fmaxf(m, srow[c]);
            float sc = expf(mOld - m);
            float l = rowL[tid] * sc;
#pragma unroll 8
            for (int c = 0; c < 64; c++) {
                float pv = expf(srow[c] - m);
                srow[c] = pv;
                l += pv;
            }
            rowM[tid] = m;
            rowL[tid] = l;
            rowScale[tid] = sc;
        }
        __syncthreads();

        // Rescale accumulators
#pragma unroll
        for (int i = 0; i < 4; i++) {
            float sc = rowScale[ty * 4 + i];
#pragma unroll
            for (int j = 0; j < 8; j++) acc[i][j] *= sc;
        }

        // Load V into the K buffer (all reads of K are done)
        for (int i = tid; i < 64 * 32; i += 256) {
            int r = i >> 5, c4 = (i & 31) << 2;
            *(float4*)&KVs[r * SQS + c4] = *(const float4*)
                &g_qkv[(size_t)(b * Tn + ts * 64 + r) * QKVN + VOFF + kvh * HD + c4];
        }
        __syncthreads();

        // O += P V : thread rows ty*4+i, cols tx*8+j
        for (int kk = 0; kk < 64; kk++) {
            float p[4];
#pragma unroll
            for (int i = 0; i < 4; i++) p[i] = Ss[(ty * 4 + i) * 65 + kk];
            float4 v1 = *(float4*)&KVs[kk * SQS + tx * 8];
            float4 v2 = *(float4*)&KVs[kk * SQS + tx * 8 + 4];
#pragma unroll
            for (int i = 0; i < 4; i++) {
                acc[i][0] += p[i] * v1.x;
                acc[i][1] += p[i] * v1.y;
                acc[i][2] += p[i] * v1.z;
                acc[i][3] += p[i] * v1.w;
                acc[i][4] += p[i] * v2.x;
                acc[i][5] += p[i] * v2.y;
                acc[i][6] += p[i] * v2.z;
                acc[i][7] += p[i] * v2.w;
            }
        }
        __syncthreads();
    }

    // Epilogue: normalize, write encoded
#pragma unroll
    for (int i = 0; i < 4; i++) {
        float inv = 1.0f / rowL[ty * 4 + i];
        float* orow =
            g_enc + (size_t)(rowBase + ty * 4 + i) * ENCN + n * HD + tx * 8;
        float4 o1 = {acc[i][0] * inv, acc[i][1] * inv, acc[i][2] * inv,
                     acc[i][3] * inv};
        float4 o2 = {acc[i][4] * inv, acc[i][5] * inv, acc[i][6] * inv,
                     acc[i][7] * inv};
        *(float4*)orow = o1;
        *(float4*)(orow + 4) = o2;
    }
}

// ---------------------------------------------------------------------------
extern "C" void kernel_launch(void* const* d_in, const int* in_sizes, int n_in,
                              void* d_out, int out_size) {
    (void)in_sizes; (void)n_in; (void)out_size;
    const float* x = (const float*)d_in[0];
    const int* positions = (const int*)d_in[1];
    // d_in[2] = attn_mask (causal, hardcoded)
    const float* w_q = (const float*)d_in[3];
    const float* w_kv = (const float*)d_in[4];
    const float* w_out = (const float*)d_in[5];
    float* out = (float*)d_out;

    const int attn_smem = (64 * SQS * 2 + 64 * 65 + 192) * 4;  // 84992 B
    cudaFuncSetAttribute(attn_kernel,
                         cudaFuncAttributeMaxDynamicSharedMemorySize, attn_smem);

    void *p_wc, *p_qkv, *p_enc;
    cudaGetSymbolAddress(&p_wc, g_wc);
    cudaGetSymbolAddress(&p_qkv, g_qkv);
    cudaGetSymbolAddress(&p_enc, g_enc);

    // 1. pack weights
    {
        int total = Dm * QKVN;
        pack_w_kernel<<<(total + 255) / 256, 256>>>(w_q, w_kv);
    }
    // 2. fused QKV projection
    {
        dim3 grid(QKVN / 128, MROWS / 128);
        sgemm_kernel<<<grid, 256>>>(x, (const float*)p_wc, (float*)p_qkv,
                                    MROWS, QKVN, Dm);
    }
    // 3. RoPE (+ q scale)
    {
        int total = MROWS * (NHq + NKV) * 64;
        rope_kernel<<<(total + 255) / 256, 256>>>(positions);
    }
    // 4. attention
    {
        dim3 grid(Tn / 64, NHq, Bsz);
        attn_kernel<<<grid, 256, attn_smem>>>();
    }
    // 5. output projection (w_out is already [2048,2048] row-major)
    {
        dim3 grid(Dm / 128, MROWS / 128);
        sgemm_kernel<<<grid, 256>>>((const float*)p_enc, w_out, out,
                                    MROWS, Dm, ENCN);
    }
}

// round 2
// speedup vs baseline: 1.3766x; 1.3766x over previous
#include <cuda_runtime.h>
#include <cuda_bf16.h>
#include <math.h>

// Problem constants
#define Bsz 2
#define Tn 2048
#define Dm 2048
#define NHq 16
#define NKV 8
#define HD 128
#define MROWS (Bsz * Tn)          // 4096 tokens
#define QKVN 4096                 // 2048 q | 1024 k | 1024 v
#define KOFF 2048
#define VOFF 3072
#define ENCN 2048
#define K3 6144                   // 3x split-bf16 K dimension
#define BIG_NEG -2.3819763e38f

// Scratch (device globals: allocation-free per harness rules)
__device__ __nv_bfloat16 g_wb3[(size_t)K3 * QKVN];  // QKV weights, split-bf16 [6144][4096]
__device__ __nv_bfloat16 g_wo3[(size_t)K3 * ENCN];  // out weights, split-bf16 [6144][2048]
__device__ __nv_bfloat16 g_a3[(size_t)MROWS * K3];  // activations, split-bf16 [4096][6144]
__device__ float g_qkv[(size_t)MROWS * QKVN];       // projections, rope'd in place
__device__ float g_enc[(size_t)MROWS * ENCN];       // attention output

// ---------------------------------------------------------------------------
// Pack w_q [16,2048,128] + w_kv [2,8,2048,128] into split-bf16 [K3=6144][4096]
// Row blocks along K3: [hi | lo | hi]  (pairs with A cols [hi | hi | lo])
// ---------------------------------------------------------------------------
__global__ void pack_w3_kernel(const float* __restrict__ wq,
                               const float* __restrict__ wkv) {
    size_t idx = (size_t)blockIdx.x * blockDim.x + threadIdx.x;
    if (idx >= (size_t)K3 * QKVN) return;
    int j = (int)(idx & (QKVN - 1));
    int k3 = (int)(idx >> 12);
    int seg = k3 >> 11;          // 0: hi, 1: lo, 2: hi
    int d = k3 & 2047;
    float w;
    if (j < KOFF) {
        int n = j >> 7, h = j & 127;
        w = wq[((size_t)n * Dm + d) * HD + h];
    } else if (j < VOFF) {
        int jj = j - KOFF;
        int n = jj >> 7, h = jj & 127;
        w = wkv[((size_t)n * Dm + d) * HD + h];
    } else {
        int jj = j - VOFF;
        int n = jj >> 7, h = jj & 127;
        w = wkv[((size_t)(NKV + n) * Dm + d) * HD + h];
    }
    __nv_bfloat16 hi = __float2bfloat16(w);
    __nv_bfloat16 out;
    if (seg == 1) out = __float2bfloat16(w - __bfloat162float(hi));
    else          out = hi;
    g_wb3[idx] = out;
}

// ---------------------------------------------------------------------------
// Pack w_out [16,128,2048] (== [2048][2048] row-major) into split-bf16 [6144][2048]
// ---------------------------------------------------------------------------
__global__ void pack_wo3_kernel(const float* __restrict__ wout) {
    size_t idx = (size_t)blockIdx.x * blockDim.x + threadIdx.x;
    if (idx >= (size_t)K3 * ENCN) return;
    int d = (int)(idx & (ENCN - 1));
    int k3 = (int)(idx >> 11);
    int seg = k3 >> 11;
    int kk = k3 & 2047;
    float w = wout[(size_t)kk * ENCN + d];
    __nv_bfloat16 hi = __float2bfloat16(w);
    __nv_bfloat16 out;
    if (seg == 1) out = __float2bfloat16(w - __bfloat162float(hi));
    else          out = hi;
    g_wo3[idx] = out;
}

// ---------------------------------------------------------------------------
// Split fp32 activations [4096][2048] into g_a3 [4096][6144]: cols [hi|hi|lo]
// ---------------------------------------------------------------------------
__global__ void split3_kernel(const float* __restrict__ src) {
    size_t idx = (size_t)blockIdx.x * blockDim.x + threadIdx.x;
    if (idx >= (size_t)MROWS * 2048) return;
    int k = (int)(idx & 2047);
    int m = (int)(idx >> 11);
    float a = src[idx];
    __nv_bfloat16 hi = __float2bfloat16(a);
    __nv_bfloat16 lo = __float2bfloat16(a - __bfloat162float(hi));
    __nv_bfloat16* dst = g_a3 + (size_t)m * K3;
    dst[k] = hi;
    dst[k + 2048] = hi;
    dst[k + 4096] = lo;
}

// ---------------------------------------------------------------------------
// Split-bf16 GEMM: C[M=4096, N] = A3[4096][6144] * B3[6144][N], fp32 accum
// 128x128x32 tile, 256 threads (8 warps, 4x2), mma.sync m16n8k16 bf16,
// cp.async double-buffered smem, ldmatrix with conflict-free padded strides.
// ---------------------------------------------------------------------------
#define GBM 128
#define GBK 32
#define ASTR 40    // A smem row stride (elems): 80B -> 8 distinct banks
#define BSTR 136   // B smem row stride (elems): 272B -> 8 distinct banks

#define CPA16(dst, src) \
    asm volatile("cp.async.cg.shared.global [%0], [%1], 16;" ::"r"(dst), "l"(src))

__global__ __launch_bounds__(256, 2) void bf3_gemm_kernel(
    const __nv_bfloat16* __restrict__ A, const __nv_bfloat16* __restrict__ B,
    float* __restrict__ C, int N) {
    __shared__ __nv_bfloat16 As[2][GBM * ASTR];
    __shared__ __nv_bfloat16 Bs[2][GBK * BSTR];
    const int tid = threadIdx.x;
    const int lane = tid & 31, warp = tid >> 5;
    const int warpM = warp >> 1, warpN = warp & 1;  // 4 x 2 warp grid
    const int rowBlock = blockIdx.y * GBM, colBlock = blockIdx.x * 128;

    unsigned aSm = (unsigned)__cvta_generic_to_shared(&As[0][0]);
    unsigned bSm = (unsigned)__cvta_generic_to_shared(&Bs[0][0]);

    // Global->smem copy assignments (16B chunks, 2 per thread per operand)
    const int arow = tid >> 2, ach = (tid & 3) * 8;      // A: rows arow, arow+64
    const int brow = tid >> 4, bch = (tid & 15) * 8;     // B: rows brow, brow+16

    // Prologue: stage 0, k0 = 0
    {
        const __nv_bfloat16* s;
        s = A + (size_t)(rowBlock + arow) * K3 + ach;
        CPA16(aSm + (arow * ASTR + ach) * 2, s);
        s = A + (size_t)(rowBlock + arow + 64) * K3 + ach;
        CPA16(aSm + ((arow + 64) * ASTR + ach) * 2, s);
        s = B + (size_t)brow * N + colBlock + bch;
        CPA16(bSm + (brow * BSTR + bch) * 2, s);
        s = B + (size_t)(brow + 16) * N + colBlock + bch;
        CPA16(bSm + ((brow + 16) * BSTR + bch) * 2, s);
        asm volatile("cp.async.commit_group;");
    }

    float acc[2][8][4] = {};

    // ldmatrix lane addressing
    const int ldRow = (lane & 7) + ((lane >> 3) & 1) * 8;  // row within 16
    const int ldCol = (lane >> 4) * 8;                     // 0 or 8

    const int NIT = K3 / GBK;  // 192
    for (int it = 0; it < NIT; it++) {
        asm volatile("cp.async.wait_group 0;" ::: "memory");
        __syncthreads();
        if (it + 1 < NIT) {
            const int k0 = (it + 1) * GBK;
            const int st = (it + 1) & 1;
            unsigned aOff = aSm + st * (GBM * ASTR * 2);
            unsigned bOff = bSm + st * (GBK * BSTR * 2);
            const __nv_bfloat16* s;
            s = A + (size_t)(rowBlock + arow) * K3 + k0 + ach;
            CPA16(aOff + (arow * ASTR + ach) * 2, s);
            s = A + (size_t)(rowBlock + arow + 64) * K3 + k0 + ach;
            CPA16(aOff + ((arow + 64) * ASTR + ach) * 2, s);
            s = B + (size_t)(k0 + brow) * N + colBlock + bch;
            CPA16(bOff + (brow * BSTR + bch) * 2, s);
            s = B + (size_t)(k0 + brow + 16) * N + colBlock + bch;
            CPA16(bOff + ((brow + 16) * BSTR + bch) * 2, s);
            asm volatile("cp.async.commit_group;");
        }
        const int st = it & 1;
        unsigned aOff = aSm + st * (GBM * ASTR * 2);
        unsigned bOff = bSm + st * (GBK * BSTR * 2);
#pragma unroll
        for (int ks = 0; ks < 2; ks++) {
            unsigned af[2][4];
#pragma unroll
            for (int mt = 0; mt < 2; mt++) {
                unsigned addr =
                    aOff + ((warpM * 32 + mt * 16 + ldRow) * ASTR + ks * 16 + ldCol) * 2;
                asm volatile(
                    "ldmatrix.sync.aligned.m8n8.x4.shared.b16 {%0,%1,%2,%3}, [%4];"
                    : "=r"(af[mt][0]), "=r"(af[mt][1]), "=r"(af[mt][2]), "=r"(af[mt][3])
                    : "r"(addr));
            }
            unsigned bfr[8][2];
#pragma unroll
            for (int np = 0; np < 4; np++) {
                unsigned addr =
                    bOff + ((ks * 16 + ldRow) * BSTR + warpN * 64 + np * 16 + ldCol) * 2;
                asm volatile(
                    "ldmatrix.sync.aligned.m8n8.x4.trans.shared.b16 {%0,%1,%2,%3}, [%4];"
                    : "=r"(bfr[np * 2][0]), "=r"(bfr[np * 2][1]),
                      "=r"(bfr[np * 2 + 1][0]), "=r"(bfr[np * 2 + 1][1])
                    : "r"(addr));
            }
#pragma unroll
            for (int mt = 0; mt < 2; mt++)
#pragma unroll
                for (int nt = 0; nt < 8; nt++) {
                    asm volatile(
                        "mma.sync.aligned.m16n8k16.row.col.f32.bf16.bf16.f32 "
                        "{%0,%1,%2,%3},{%4,%5,%6,%7},{%8,%9},{%0,%1,%2,%3};"
                        : "+f"(acc[mt][nt][0]), "+f"(acc[mt][nt][1]),
                          "+f"(acc[mt][nt][2]), "+f"(acc[mt][nt][3])
                        : "r"(af[mt][0]), "r"(af[mt][1]), "r"(af[mt][2]), "r"(af[mt][3]),
                          "r"(bfr[nt][0]), "r"(bfr[nt][1]));
                }
        }
    }

    // Epilogue
    const int gid = lane >> 2, tig = lane & 3;
#pragma unroll
    for (int mt = 0; mt < 2; mt++) {
        int r0 = rowBlock + warpM * 32 + mt * 16 + gid;
#pragma unroll
        for (int nt = 0; nt < 8; nt++) {
            int c = colBlock + warpN * 64 + nt * 8 + tig * 2;
            float2 v0 = make_float2(acc[mt][nt][0], acc[mt][nt][1]);
            float2 v1 = make_float2(acc[mt][nt][2], acc[mt][nt][3]);
            *(float2*)&C[(size_t)r0 * N + c] = v0;
            *(float2*)&C[(size_t)(r0 + 8) * N + c] = v1;
        }
    }
}

// ---------------------------------------------------------------------------
// RoPE in-place on q (with 1/sqrt(HD) scale) and k inside g_qkv.
// ---------------------------------------------------------------------------
__global__ void rope_kernel(const int* __restrict__ positions) {
    int idx = blockIdx.x * blockDim.x + threadIdx.x;
    const int total = MROWS * (NHq + NKV) * 64;
    if (idx >= total) return;
    int p = idx & 63;
    int rest = idx >> 6;
    int head = rest % (NHq + NKV);
    int m = rest / (NHq + NKV);
    float t = (float)positions[m];
    float frac = (float)(2 * p) * (1.0f / 128.0f);
    float timescale = powf(10000.0f, frac);
    float ang = t / timescale;
    float s, c;
    sincosf(ang, &s, &c);
    int col = (head < NHq) ? head * HD : KOFF + (head - NHq) * HD;
    float scale = (head < NHq) ? 0.08838834764831845f : 1.0f;  // 128^-0.5
    float* base = g_qkv + (size_t)m * QKVN + col;
    float x1 = base[p], x2 = base[p + 64];
    base[p] = (x1 * c - x2 * s) * scale;
    base[p + 64] = (x2 * c + x1 * s) * scale;
}

// ---------------------------------------------------------------------------
// Flash attention (fp32): block = (q-tile 64 rows, head, batch); 256 threads.
// ---------------------------------------------------------------------------
#define SQS 132

__global__ __launch_bounds__(256) void attn_kernel() {
    extern __shared__ float sm[];
    float* Qs = sm;                      // 64*132
    float* KVs = Qs + 64 * SQS;          // 64*132
    float* Ss = KVs + 64 * SQS;          // 64*65
    float* rowM = Ss + 64 * 65;
    float* rowL = rowM + 64;
    float* rowScale = rowL + 64;

    int tq = blockIdx.x;
    int n = blockIdx.y;
    int b = blockIdx.z;
    int kvh = n >> 1;
    int tid = threadIdx.x;
    int tx = tid & 15, ty = tid >> 4;
    int rowBase = b * Tn + tq * 64;

    for (int i = tid; i < 64 * 32; i += 256) {
        int r = i >> 5, c4 = (i & 31) << 2;
        *(float4*)&Qs[r * SQS + c4] =
            *(const float4*)&g_qkv[(size_t)(rowBase + r) * QKVN + n * HD + c4];
    }
    if (tid < 64) { rowM[tid] = -3.4e38f; rowL[tid] = 0.f; }

    float acc[4][8];
#pragma unroll
    for (int i = 0; i < 4; i++)
#pragma unroll
        for (int j = 0; j < 8; j++) acc[i][j] = 0.f;
    __syncthreads();

    for (int ts = 0; ts <= tq; ts++) {
        for (int i = tid; i < 64 * 32; i += 256) {
            int r = i >> 5, c4 = (i & 31) << 2;
            *(float4*)&KVs[r * SQS + c4] = *(const float4*)
                &g_qkv[(size_t)(b * Tn + ts * 64 + r) * QKVN + KOFF + kvh * HD + c4];
        }
        __syncthreads();

        float s4[4][4];
#pragma unroll
        for (int i = 0; i < 4; i++)
#pragma unroll
            for (int j = 0; j < 4; j++) s4[i][j] = 0.f;
#pragma unroll 2
        for (int h = 0; h < HD; h += 4) {
            float4 qv[4], kv[4];
#pragma unroll
            for (int i = 0; i < 4; i++)
                qv[i] = *(float4*)&Qs[(ty * 4 + i) * SQS + h];
#pragma unroll
            for (int j = 0; j < 4; j++)
                kv[j] = *(float4*)&KVs[(tx * 4 + j) * SQS + h];
#pragma unroll
            for (int i = 0; i < 4; i++)
#pragma unroll
                for (int j = 0; j < 4; j++)
                    s4[i][j] += qv[i].x * kv[j].x + qv[i].y * kv[j].y +
                                qv[i].z * kv[j].z + qv[i].w * kv[j].w;
        }

#pragma unroll
        for (int i = 0; i < 4; i++) {
            int gr = tq * 64 + ty * 4 + i;
#pragma unroll
            for (int j = 0; j < 4; j++) {
                int gc = ts * 64 + tx * 4 + j;
                float v = tanhf(s4[i][j] * 0.02f) * 50.0f;
                if (gc > gr) v = BIG_NEG;
                Ss[(ty * 4 + i) * 65 + tx * 4 + j] = v;
            }
        }
        __syncthreads();

        if (tid < 64) {
            float mOld = rowM[tid];
            float m = mOld;
            float* srow = Ss + tid * 65;
#pragma unroll 8
            for (int c = 0; c < 64; c++) m = fmaxf(m, srow[c]);
            float sc = expf(mOld - m);
            float l = rowL[tid] * sc;
#pragma unroll 8
            for (int c = 0; c < 64; c++) {
                float pv = expf(srow[c] - m);
                srow[c] = pv;
                l += pv;
            }
            rowM[tid] = m;
            rowL[tid] = l;
            rowScale[tid] = sc;
        }
        __syncthreads();

#pragma unroll
        for (int i = 0; i < 4; i++) {
            float sc = rowScale[ty * 4 + i];
#pragma unroll
            for (int j = 0; j < 8; j++) acc[i][j] *= sc;
        }

        for (int i = tid; i < 64 * 32; i += 256) {
            int r = i >> 5, c4 = (i & 31) << 2;
            *(float4*)&KVs[r * SQS + c4] = *(const float4*)
                &g_qkv[(size_t)(b * Tn + ts * 64 + r) * QKVN + VOFF + kvh * HD + c4];
        }
        __syncthreads();

        for (int kk = 0; kk < 64; kk++) {
            float p[4];
#pragma unroll
            for (int i = 0; i < 4; i++) p[i] = Ss[(ty * 4 + i) * 65 + kk];
            float4 v1 = *(float4*)&KVs[kk * SQS + tx * 8];
            float4 v2 = *(float4*)&KVs[kk * SQS + tx * 8 + 4];
#pragma unroll
            for (int i = 0; i < 4; i++) {
                acc[i][0] += p[i] * v1.x;
                acc[i][1] += p[i] * v1.y;
                acc[i][2] += p[i] * v1.z;
                acc[i][3] += p[i] * v1.w;
                acc[i][4] += p[i] * v2.x;
                acc[i][5] += p[i] * v2.y;
                acc[i][6] += p[i] * v2.z;
                acc[i][7] += p[i] * v2.w;
            }
        }
        __syncthreads();
    }

#pragma unroll
    for (int i = 0; i < 4; i++) {
        float inv = 1.0f / rowL[ty * 4 + i];
        float* orow =
            g_enc + (size_t)(rowBase + ty * 4 + i) * ENCN + n * HD + tx * 8;
        float4 o1 = {acc[i][0] * inv, acc[i][1] * inv, acc[i][2] * inv,
                     acc[i][3] * inv};
        float4 o2 = {acc[i][4] * inv, acc[i][5] * inv, acc[i][6] * inv,
                     acc[i][7] * inv};
        *(float4*)orow = o1;
        *(float4*)(orow + 4) = o2;
    }
}

// ---------------------------------------------------------------------------
extern "C" void kernel_launch(void* const* d_in, const int* in_sizes, int n_in,
                              void* d_out, int out_size) {
    (void)in_sizes; (void)n_in; (void)out_size;
    const float* x = (const float*)d_in[0];
    const int* positions = (const int*)d_in[1];
    // d_in[2] = attn_mask (causal, hardcoded)
    const float* w_q = (const float*)d_in[3];
    const float* w_kv = (const float*)d_in[4];
    const float* w_out = (const float*)d_in[5];
    float* out = (float*)d_out;

    const int attn_smem = (64 * SQS * 2 + 64 * 65 + 192) * 4;
    cudaFuncSetAttribute(attn_kernel,
                         cudaFuncAttributeMaxDynamicSharedMemorySize, attn_smem);

    void *p_qkv, *p_enc, *p_a3, *p_wb3, *p_wo3;
    cudaGetSymbolAddress(&p_qkv, g_qkv);
    cudaGetSymbolAddress(&p_enc, g_enc);
    cudaGetSymbolAddress(&p_a3, g_a3);
    cudaGetSymbolAddress(&p_wb3, g_wb3);
    cudaGetSymbolAddress(&p_wo3, g_wo3);

    // 1. pack weights into split-bf16
    {
        size_t total = (size_t)K3 * QKVN;
        pack_w3_kernel<<<(unsigned)((total + 255) / 256), 256>>>(w_q, w_kv);
    }
    {
        size_t total = (size_t)K3 * ENCN;
        pack_wo3_kernel<<<(unsigned)((total + 255) / 256), 256>>>(w_out);
    }
    // 2. split x into bf16 hi/lo triple
    {
        size_t total = (size_t)MROWS * 2048;
        split3_kernel<<<(unsigned)((total + 255) / 256), 256>>>(x);
    }
    // 3. fused QKV projection (tensor cores)
    {
        dim3 grid(QKVN / 128, MROWS / 128);
        bf3_gemm_kernel<<<grid, 256>>>((const __nv_bfloat16*)p_a3,
                                       (const __nv_bfloat16*)p_wb3,
                                       (float*)p_qkv, QKVN);
    }
    // 4. RoPE (+ q scale)
    {
        int total = MROWS * (NHq + NKV) * 64;
        rope_kernel<<<(total + 255) / 256, 256>>>(positions);
    }
    // 5. attention
    {
        dim3 grid(Tn / 64, NHq, Bsz);
        attn_kernel<<<grid, 256, attn_smem>>>();
    }
    // 6. split encoded into bf16 hi/lo triple
    {
        size_t total = (size_t)MROWS * 2048;
        split3_kernel<<<(unsigned)((total + 255) / 256), 256>>>(
            (const float*)p_enc);
    }
    // 7. output projection (tensor cores)
    {
        dim3 grid(ENCN / 128, MROWS / 128);
        bf3_gemm_kernel<<<grid, 256>>>((const __nv_bfloat16*)p_a3,
                                       (const __nv_bfloat16*)p_wo3, out, ENCN);
    }
}

// round 4
// speedup vs baseline: 2.7657x; 2.0091x over previous
#include <cuda_runtime.h>
#include <cuda_bf16.h>
#include <math.h>

// Problem constants
#define Bsz 2
#define Tn 2048
#define Dm 2048
#define NHq 16
#define NKV 8
#define HD 128
#define MROWS (Bsz * Tn)          // 4096 tokens
#define QKVN 4096                 // 2048 q | 1024 k | 1024 v
#define KOFF 2048
#define VOFF 3072
#define ENCN 2048
#define K3 6144                   // 3x split-bf16 K dimension
#define BIG_NEG -2.3819763e38f

// Scratch (device globals: allocation-free per harness rules)
__device__ __nv_bfloat16 g_wb3[(size_t)K3 * QKVN];  // QKV weights, split-bf16
__device__ __nv_bfloat16 g_wo3[(size_t)K3 * ENCN];  // out weights, split-bf16
__device__ __nv_bfloat16 g_a3[(size_t)MROWS * K3];  // activations, split-bf16
__device__ float g_qkv[(size_t)MROWS * QKVN];       // projections, rope'd in place
__device__ __nv_bfloat16 g_sh[(size_t)MROWS * QKVN];  // qkv hi plane
__device__ __nv_bfloat16 g_sl[(size_t)MROWS * QKVN];  // qkv lo plane
__device__ float g_enc[(size_t)MROWS * ENCN];       // attention output

// ---------------------------------------------------------------------------
#define CPA16(dst, src) \
    asm volatile("cp.async.cg.shared.global [%0], [%1], 16;" ::"r"(dst), "l"(src))
#define LDSM4(r, addr)                                                        \
    asm volatile("ldmatrix.sync.aligned.m8n8.x4.shared.b16 {%0,%1,%2,%3},[%4];" \
                 : "=r"((r)[0]), "=r"((r)[1]), "=r"((r)[2]), "=r"((r)[3])     \
                 : "r"(addr))
#define LDSM4T(r, addr)                                                       \
    asm volatile(                                                             \
        "ldmatrix.sync.aligned.m8n8.x4.trans.shared.b16 {%0,%1,%2,%3},[%4];"  \
        : "=r"((r)[0]), "=r"((r)[1]), "=r"((r)[2]), "=r"((r)[3])              \
        : "r"(addr))
#define MMA_B16(d, a, b0, b1)                                                 \
    asm volatile(                                                             \
        "mma.sync.aligned.m16n8k16.row.col.f32.bf16.bf16.f32 "                \
        "{%0,%1,%2,%3},{%4,%5,%6,%7},{%8,%9},{%0,%1,%2,%3};"                  \
        : "+f"((d)[0]), "+f"((d)[1]), "+f"((d)[2]), "+f"((d)[3])              \
        : "r"((a)[0]), "r"((a)[1]), "r"((a)[2]), "r"((a)[3]), "r"(b0), "r"(b1))

__device__ __forceinline__ unsigned pack2bf(float a, float b) {
    __nv_bfloat162 h = __floats2bfloat162_rn(a, b);
    return *(unsigned*)&h;
}

// ---------------------------------------------------------------------------
// Pack w_q + w_kv into split-bf16 [K3=6144][4096]: row blocks [hi | lo | hi]
// ---------------------------------------------------------------------------
__global__ void pack_w3_kernel(const float* __restrict__ wq,
                               const float* __restrict__ wkv) {
    size_t idx = (size_t)blockIdx.x * blockDim.x + threadIdx.x;
    if (idx >= (size_t)K3 * QKVN) return;
    int j = (int)(idx & (QKVN - 1));
    int k3 = (int)(idx >> 12);
    int seg = k3 >> 11;
    int d = k3 & 2047;
    float w;
    if (j < KOFF) {
        int n = j >> 7, h = j & 127;
        w = wq[((size_t)n * Dm + d) * HD + h];
    } else if (j < VOFF) {
        int jj = j - KOFF;
        int n = jj >> 7, h = jj & 127;
        w = wkv[((size_t)n * Dm + d) * HD + h];
    } else {
        int jj = j - VOFF;
        int n = jj >> 7, h = jj & 127;
        w = wkv[((size_t)(NKV + n) * Dm + d) * HD + h];
    }
    __nv_bfloat16 hi = __float2bfloat16(w);
    g_wb3[idx] = (seg == 1) ? __float2bfloat16(w - __bfloat162float(hi)) : hi;
}

__global__ void pack_wo3_kernel(const float* __restrict__ wout) {
    size_t idx = (size_t)blockIdx.x * blockDim.x + threadIdx.x;
    if (idx >= (size_t)K3 * ENCN) return;
    int d = (int)(idx & (ENCN - 1));
    int k3 = (int)(idx >> 11);
    int seg = k3 >> 11;
    int kk = k3 & 2047;
    float w = wout[(size_t)kk * ENCN + d];
    __nv_bfloat16 hi = __float2bfloat16(w);
    g_wo3[idx] = (seg == 1) ? __float2bfloat16(w - __bfloat162float(hi)) : hi;
}

// Split fp32 [4096][2048] into g_a3 [4096][6144]: cols [hi|hi|lo]
__global__ void split3_kernel(const float* __restrict__ src) {
    size_t idx = (size_t)blockIdx.x * blockDim.x + threadIdx.x;
    if (idx >= (size_t)MROWS * 2048) return;
    int k = (int)(idx & 2047);
    int m = (int)(idx >> 11);
    float a = src[idx];
    __nv_bfloat16 hi = __float2bfloat16(a);
    __nv_bfloat16 lo = __float2bfloat16(a - __bfloat162float(hi));
    __nv_bfloat16* dst = g_a3 + (size_t)m * K3;
    dst[k] = hi;
    dst[k + 2048] = hi;
    dst[k + 4096] = lo;
}

// Split rope'd g_qkv fp32 [4096][4096] into bf16 hi/lo planes
__global__ void splitqkv_kernel() {
    size_t i4 = ((size_t)blockIdx.x * blockDim.x + threadIdx.x) * 4;
    if (i4 >= (size_t)MROWS * QKVN) return;
    float4 v = *(const float4*)&g_qkv[i4];
    float vv[4] = {v.x, v.y, v.z, v.w};
    __nv_bfloat16 h[4], l[4];
#pragma unroll
    for (int i = 0; i < 4; i++) {
        h[i] = __float2bfloat16(vv[i]);
        l[i] = __float2bfloat16(vv[i] - __bfloat162float(h[i]));
    }
    *(__nv_bfloat162*)&g_sh[i4] = *(__nv_bfloat162*)&h[0];
    *(__nv_bfloat162*)&g_sh[i4 + 2] = *(__nv_bfloat162*)&h[2];
    *(__nv_bfloat162*)&g_sl[i4] = *(__nv_bfloat162*)&l[0];
    *(__nv_bfloat162*)&g_sl[i4 + 2] = *(__nv_bfloat162*)&l[2];
}

// ---------------------------------------------------------------------------
// Split-bf16 GEMM (unchanged)
// ---------------------------------------------------------------------------
#define GBM 128
#define GBK 32
#define ASTR 40
#define BSTR 136

__global__ __launch_bounds__(256, 2) void bf3_gemm_kernel(
    const __nv_bfloat16* __restrict__ A, const __nv_bfloat16* __restrict__ B,
    float* __restrict__ C, int N) {
    __shared__ __nv_bfloat16 As[2][GBM * ASTR];
    __shared__ __nv_bfloat16 Bs[2][GBK * BSTR];
    const int tid = threadIdx.x;
    const int lane = tid & 31, warp = tid >> 5;
    const int warpM = warp >> 1, warpN = warp & 1;
    const int rowBlock = blockIdx.y * GBM, colBlock = blockIdx.x * 128;

    unsigned aSm = (unsigned)__cvta_generic_to_shared(&As[0][0]);
    unsigned bSm = (unsigned)__cvta_generic_to_shared(&Bs[0][0]);

    const int arow = tid >> 2, ach = (tid & 3) * 8;
    const int brow = tid >> 4, bch = (tid & 15) * 8;

    {
        const __nv_bfloat16* s;
        s = A + (size_t)(rowBlock + arow) * K3 + ach;
        CPA16(aSm + (arow * ASTR + ach) * 2, s);
        s = A + (size_t)(rowBlock + arow + 64) * K3 + ach;
        CPA16(aSm + ((arow + 64) * ASTR + ach) * 2, s);
        s = B + (size_t)brow * N + colBlock + bch;
        CPA16(bSm + (brow * BSTR + bch) * 2, s);
        s = B + (size_t)(brow + 16) * N + colBlock + bch;
        CPA16(bSm + ((brow + 16) * BSTR + bch) * 2, s);
        asm volatile("cp.async.commit_group;");
    }

    float acc[2][8][4] = {};
    const int ldRow = (lane & 7) + ((lane >> 3) & 1) * 8;
    const int ldCol = (lane >> 4) * 8;

    const int NIT = K3 / GBK;
    for (int it = 0; it < NIT; it++) {
        asm volatile("cp.async.wait_group 0;" ::: "memory");
        __syncthreads();
        if (it + 1 < NIT) {
            const int k0 = (it + 1) * GBK;
            const int st = (it + 1) & 1;
            unsigned aOff = aSm + st * (GBM * ASTR * 2);
            unsigned bOff = bSm + st * (GBK * BSTR * 2);
            const __nv_bfloat16* s;
            s = A + (size_t)(rowBlock + arow) * K3 + k0 + ach;
            CPA16(aOff + (arow * ASTR + ach) * 2, s);
            s = A + (size_t)(rowBlock + arow + 64) * K3 + k0 + ach;
            CPA16(aOff + ((arow + 64) * ASTR + ach) * 2, s);
            s = B + (size_t)(k0 + brow) * N + colBlock + bch;
            CPA16(bOff + (brow * BSTR + bch) * 2, s);
            s = B + (size_t)(k0 + brow + 16) * N + colBlock + bch;
            CPA16(bOff + ((brow + 16) * BSTR + bch) * 2, s);
            asm volatile("cp.async.commit_group;");
        }
        const int st = it & 1;
        unsigned aOff = aSm + st * (GBM * ASTR * 2);
        unsigned bOff = bSm + st * (GBK * BSTR * 2);
#pragma unroll
        for (int ks = 0; ks < 2; ks++) {
            unsigned af[2][4];
#pragma unroll
            for (int mt = 0; mt < 2; mt++) {
                unsigned addr =
                    aOff + ((warpM * 32 + mt * 16 + ldRow) * ASTR + ks * 16 + ldCol) * 2;
                LDSM4(af[mt], addr);
            }
            unsigned bfr[8][2];
#pragma unroll
            for (int np = 0; np < 4; np++) {
                unsigned addr =
                    bOff + ((ks * 16 + ldRow) * BSTR + warpN * 64 + np * 16 + ldCol) * 2;
                asm volatile(
                    "ldmatrix.sync.aligned.m8n8.x4.trans.shared.b16 {%0,%1,%2,%3}, [%4];"
                    : "=r"(bfr[np * 2][0]), "=r"(bfr[np * 2][1]),
                      "=r"(bfr[np * 2 + 1][0]), "=r"(bfr[np * 2 + 1][1])
                    : "r"(addr));
            }
#pragma unroll
            for (int mt = 0; mt < 2; mt++)
#pragma unroll
                for (int nt = 0; nt < 8; nt++)
                    MMA_B16(acc[mt][nt], af[mt], bfr[nt][0], bfr[nt][1]);
        }
    }

    const int gid = lane >> 2, tig = lane & 3;
#pragma unroll
    for (int mt = 0; mt < 2; mt++) {
        int r0 = rowBlock + warpM * 32 + mt * 16 + gid;
#pragma unroll
        for (int nt = 0; nt < 8; nt++) {
            int c = colBlock + warpN * 64 + nt * 8 + tig * 2;
            *(float2*)&C[(size_t)r0 * N + c] =
                make_float2(acc[mt][nt][0], acc[mt][nt][1]);
            *(float2*)&C[(size_t)(r0 + 8) * N + c] =
                make_float2(acc[mt][nt][2], acc[mt][nt][3]);
        }
    }
}

// ---------------------------------------------------------------------------
// RoPE in-place (unchanged)
// ---------------------------------------------------------------------------
__global__ void rope_kernel(const int* __restrict__ positions) {
    int idx = blockIdx.x * blockDim.x + threadIdx.x;
    const int total = MROWS * (NHq + NKV) * 64;
    if (idx >= total) return;
    int p = idx & 63;
    int rest = idx >> 6;
    int head = rest % (NHq + NKV);
    int m = rest / (NHq + NKV);
    float t = (float)positions[m];
    float frac = (float)(2 * p) * (1.0f / 128.0f);
    float timescale = powf(10000.0f, frac);
    float ang = t / timescale;
    float s, c;
    sincosf(ang, &s, &c);
    int col = (head < NHq) ? head * HD : KOFF + (head - NHq) * HD;
    float scale = (head < NHq) ? 0.08838834764831845f : 1.0f;
    float* base = g_qkv + (size_t)m * QKVN + col;
    float x1 = base[p], x2 = base[p + 64];
    base[p] = (x1 * c - x2 * s) * scale;
    base[p + 64] = (x2 * c + x1 * s) * scale;
}

// ---------------------------------------------------------------------------
// Tensor-core flash attention, split-bf16 3-term.
// CTA: 128 q-rows x 1 head x 1 batch; 256 threads (8 warps x 16 rows).
// Smem per stage (byte offsets): Kh@0, Kl@ABUF*2, Vh@ABUF*4, Vl@ABUF*6.
// ---------------------------------------------------------------------------
#define ATS 136                      // smem row stride (elems)
#define ABUF (64 * ATS)              // one 64-row buffer (elems)
#define ASTG (4 * ABUF)              // Kh,Kl,Vh,Vl per stage (elems)

__global__ __launch_bounds__(256, 1) void attn_mma_kernel() {
    extern __shared__ __align__(16) __nv_bfloat16 sm[];
    const int tid = threadIdx.x, lane = tid & 31, warp = tid >> 5;
    const int tq = 15 - blockIdx.x;        // heavy tiles first
    const int n = blockIdx.y, b = blockIdx.z, kvh = n >> 1;
    const unsigned smBase = (unsigned)__cvta_generic_to_shared(sm);

    const int kvRow = tid >> 2;
    const int kvCh = (tid & 3) * 32;
    const int qRow = tid >> 1;
    const int qCh = (tid & 1) * 64;

    const size_t kRowBase = (size_t)(b * Tn) * QKVN + KOFF + kvh * HD;
    const size_t vRowBase = (size_t)(b * Tn) * QKVN + VOFF + kvh * HD;

    // Prologue: Q -> stage1 region (Qh at ASTG, Ql at ASTG + 2*ABUF); KV0 -> stage0
    {
        size_t qsrc = (size_t)(b * Tn + tq * 128 + qRow) * QKVN + n * HD + qCh;
#pragma unroll
        for (int c = 0; c < 8; c++) {
            CPA16(smBase + (ASTG + qRow * ATS + qCh + c * 8) * 2, g_sh + qsrc + c * 8);
            CPA16(smBase + (ASTG + 2 * ABUF + qRow * ATS + qCh + c * 8) * 2,
                  g_sl + qsrc + c * 8);
        }
        size_t kr = kRowBase + (size_t)kvRow * QKVN + kvCh;
        size_t vr = vRowBase + (size_t)kvRow * QKVN + kvCh;
#pragma unroll
        for (int c = 0; c < 4; c++) {
            CPA16(smBase + (0 * ABUF + kvRow * ATS + kvCh + c * 8) * 2, g_sh + kr + c * 8);
            CPA16(smBase + (1 * ABUF + kvRow * ATS + kvCh + c * 8) * 2, g_sl + kr + c * 8);
            CPA16(smBase + (2 * ABUF + kvRow * ATS + kvCh + c * 8) * 2, g_sh + vr + c * 8);
            CPA16(smBase + (3 * ABUF + kvRow * ATS + kvCh + c * 8) * 2, g_sl + vr + c * 8);
        }
        asm volatile("cp.async.commit_group;");
    }
    asm volatile("cp.async.wait_group 0;" ::: "memory");
    __syncthreads();

    // Preload Q fragments (reused across all KV tiles)
    unsigned qfH[8][4], qfL[8][4];
    {
        const int aRow = lane & 15;
        const int aCol = (lane >> 4) * 8;
#pragma unroll
        for (int kc = 0; kc < 8; kc++) {
            LDSM4(qfH[kc],
                  smBase + (ASTG + (warp * 16 + aRow) * ATS + kc * 16 + aCol) * 2);
            LDSM4(qfL[kc],
                  smBase + (ASTG + 2 * ABUF + (warp * 16 + aRow) * ATS + kc * 16 + aCol) * 2);
        }
    }
    __syncthreads();  // Q region may now be overwritten by prefetch

    float oacc[16][4] = {};
    float m0 = -1e30f, m1 = -1e30f, l0 = 0.f, l1 = 0.f;
    const int gid = lane >> 2, tig = lane & 3;
    const int gr0 = tq * 128 + warp * 16 + gid;

    const int bkRow = ((lane >> 4) & 1) * 8 + (lane & 7);
    const int bkCol = ((lane >> 3) & 1) * 8;
    const int vRow = ((lane >> 3) & 1) * 8 + (lane & 7);
    const int vCol = ((lane >> 4) & 1) * 8;

    const int nTiles = 2 * tq + 2;
    for (int ts = 0; ts < nTiles; ts++) {
        const int stage = ts & 1;
        const unsigned stg = smBase + stage * (ASTG * 2);
        if (ts > 0) {
            asm volatile("cp.async.wait_group 0;" ::: "memory");
            __syncthreads();
        }
        if (ts + 1 < nTiles) {
            const unsigned pst = smBase + (stage ^ 1) * (ASTG * 2);
            size_t kr = kRowBase + (size_t)((ts + 1) * 64 + kvRow) * QKVN + kvCh;
            size_t vr = vRowBase + (size_t)((ts + 1) * 64 + kvRow) * QKVN + kvCh;
#pragma unroll
            for (int c = 0; c < 4; c++) {
                CPA16(pst + (0 * ABUF + kvRow * ATS + kvCh + c * 8) * 2, g_sh + kr + c * 8);
                CPA16(pst + (1 * ABUF + kvRow * ATS + kvCh + c * 8) * 2, g_sl + kr + c * 8);
                CPA16(pst + (2 * ABUF + kvRow * ATS + kvCh + c * 8) * 2, g_sh + vr + c * 8);
                CPA16(pst + (3 * ABUF + kvRow * ATS + kvCh + c * 8) * 2, g_sl + vr + c * 8);
            }
            asm volatile("cp.async.commit_group;");
        }

        // S = softcap(Q K^T), 3-term split: Qh*Kh, Qh*Kl, Ql*Kh
        float sa[8][4] = {};
#pragma unroll
        for (int pass = 0; pass < 3; pass++) {
            const unsigned kbuf = stg + ((pass == 1) ? ABUF * 2 : 0);  // byte off: Kl or Kh
#pragma unroll
            for (int kc = 0; kc < 8; kc++) {
                const unsigned (*af)[4] = (pass == 2) ? qfL : qfH;
#pragma unroll
                for (int ntp = 0; ntp < 4; ntp++) {
                    unsigned bf[4];
                    LDSM4(bf, kbuf + ((ntp * 16 + bkRow) * ATS + kc * 16 + bkCol) * 2);
                    MMA_B16(sa[2 * ntp], af[kc], bf[0], bf[1]);
                    MMA_B16(sa[2 * ntp + 1], af[kc], bf[2], bf[3]);
                }
            }
        }

        // Softcap + causal mask + online softmax
        const bool needMask = (ts * 64 + 63) > (tq * 128 + warp * 16);
        float tm0 = -1e30f, tm1 = -1e30f;
#pragma unroll
        for (int nt = 0; nt < 8; nt++) {
#pragma unroll
            for (int j = 0; j < 4; j++) {
                float x = fminf(fmaxf(sa[nt][j] * 0.02f, -8.f), 8.f);
                float e = __expf(2.f * x);
                float v = 50.f * __fdividef(e - 1.f, e + 1.f);
                if (needMask) {
                    int gc = ts * 64 + nt * 8 + tig * 2 + (j & 1);
                    int gr = gr0 + ((j >= 2) ? 8 : 0);
                    if (gc > gr) v = BIG_NEG;
                }
                sa[nt][j] = v;
                if (j < 2) tm0 = fmaxf(tm0, v);
                else       tm1 = fmaxf(tm1, v);
            }
        }
        tm0 = fmaxf(tm0, __shfl_xor_sync(0xffffffff, tm0, 1));
        tm0 = fmaxf(tm0, __shfl_xor_sync(0xffffffff, tm0, 2));
        tm1 = fmaxf(tm1, __shfl_xor_sync(0xffffffff, tm1, 1));
        tm1 = fmaxf(tm1, __shfl_xor_sync(0xffffffff, tm1, 2));
        float mn0 = fmaxf(m0, tm0), mn1 = fmaxf(m1, tm1);
        float sc0 = __expf(m0 - mn0), sc1 = __expf(m1 - mn1);
        m0 = mn0; m1 = mn1;
        l0 *= sc0; l1 *= sc1;
#pragma unroll
        for (int nt = 0; nt < 8; nt++) {
            float p0 = __expf(sa[nt][0] - mn0);
            float p1 = __expf(sa[nt][1] - mn0);
            float p2 = __expf(sa[nt][2] - mn1);
            float p3 = __expf(sa[nt][3] - mn1);
            sa[nt][0] = p0; sa[nt][1] = p1; sa[nt][2] = p2; sa[nt][3] = p3;
            l0 += p0 + p1; l1 += p2 + p3;
        }
#pragma unroll
        for (int nt = 0; nt < 16; nt++) {
            oacc[nt][0] *= sc0; oacc[nt][1] *= sc0;
            oacc[nt][2] *= sc1; oacc[nt][3] *= sc1;
        }

        // Pack P into A fragments (hi + lo)
        unsigned phf[4][4], plf[4][4];
#pragma unroll
        for (int kc = 0; kc < 4; kc++) {
            float c00 = sa[2 * kc][0], c01 = sa[2 * kc][1];
            float c02 = sa[2 * kc][2], c03 = sa[2 * kc][3];
            float c10 = sa[2 * kc + 1][0], c11 = sa[2 * kc + 1][1];
            float c12 = sa[2 * kc + 1][2], c13 = sa[2 * kc + 1][3];
            phf[kc][0] = pack2bf(c00, c01);
            phf[kc][1] = pack2bf(c02, c03);
            phf[kc][2] = pack2bf(c10, c11);
            phf[kc][3] = pack2bf(c12, c13);
#pragma unroll
            for (int r = 0; r < 4; r++) {
                __nv_bfloat162 hv = *(__nv_bfloat162*)&phf[kc][r];
                float2 hf = __bfloat1622float2(hv);
                float a0, a1;
                if (r == 0) { a0 = c00; a1 = c01; }
                else if (r == 1) { a0 = c02; a1 = c03; }
                else if (r == 2) { a0 = c10; a1 = c11; }
                else { a0 = c12; a1 = c13; }
                plf[kc][r] = pack2bf(a0 - hf.x, a1 - hf.y);
            }
        }

        // O += P V, 3-term split: Ph*Vh, Ph*Vl, Pl*Vh
        // BYTE offsets: Vh @ ABUF*4, Vl @ ABUF*6 (was the round-3 bug)
#pragma unroll
        for (int pass = 0; pass < 3; pass++) {
            const unsigned vbuf = stg + ((pass == 1) ? ABUF * 6 : ABUF * 4);
#pragma unroll
            for (int kc = 0; kc < 4; kc++) {
                const unsigned (*pf)[4] = (pass == 2) ? plf : phf;
#pragma unroll
                for (int hp = 0; hp < 8; hp++) {
                    unsigned bf[4];
                    LDSM4T(bf, vbuf + ((kc * 16 + vRow) * ATS + hp * 16 + vCol) * 2);
                    MMA_B16(oacc[2 * hp], pf[kc], bf[0], bf[1]);
                    MMA_B16(oacc[2 * hp + 1], pf[kc], bf[2], bf[3]);
                }
            }
        }
        __syncthreads();
    }

    // Epilogue
    l0 += __shfl_xor_sync(0xffffffff, l0, 1);
    l0 += __shfl_xor_sync(0xffffffff, l0, 2);
    l1 += __shfl_xor_sync(0xffffffff, l1, 1);
    l1 += __shfl_xor_sync(0xffffffff, l1, 2);
    float inv0 = 1.f / l0, inv1 = 1.f / l1;
    const size_t row0 = (size_t)(b * Tn + tq * 128 + warp * 16 + gid);
#pragma unroll
    for (int nt = 0; nt < 16; nt++) {
        int h = n * HD + nt * 8 + tig * 2;
        *(float2*)&g_enc[row0 * ENCN + h] =
            make_float2(oacc[nt][0] * inv0, oacc[nt][1] * inv0);
        *(float2*)&g_enc[(row0 + 8) * ENCN + h] =
            make_float2(oacc[nt][2] * inv1, oacc[nt][3] * inv1);
    }
}

// ---------------------------------------------------------------------------
extern "C" void kernel_launch(void* const* d_in, const int* in_sizes, int n_in,
                              void* d_out, int out_size) {
    (void)in_sizes; (void)n_in; (void)out_size;
    const float* x = (const float*)d_in[0];
    const int* positions = (const int*)d_in[1];
    const float* w_q = (const float*)d_in[3];
    const float* w_kv = (const float*)d_in[4];
    const float* w_out = (const float*)d_in[5];
    float* out = (float*)d_out;

    const int attn_smem = 2 * ASTG * 2;  // bytes
    cudaFuncSetAttribute(attn_mma_kernel,
                         cudaFuncAttributeMaxDynamicSharedMemorySize, attn_smem);

    void *p_qkv, *p_enc, *p_a3, *p_wb3, *p_wo3;
    cudaGetSymbolAddress(&p_qkv, g_qkv);
    cudaGetSymbolAddress(&p_enc, g_enc);
    cudaGetSymbolAddress(&p_a3, g_a3);
    cudaGetSymbolAddress(&p_wb3, g_wb3);
    cudaGetSymbolAddress(&p_wo3, g_wo3);

    {
        size_t total = (size_t)K3 * QKVN;
        pack_w3_kernel<<<(unsigned)((total + 255) / 256), 256>>>(w_q, w_kv);
    }
    {
        size_t total = (size_t)K3 * ENCN;
        pack_wo3_kernel<<<(unsigned)((total + 255) / 256), 256>>>(w_out);
    }
    {
        size_t total = (size_t)MROWS * 2048;
        split3_kernel<<<(unsigned)((total + 255) / 256), 256>>>(x);
    }
    {
        dim3 grid(QKVN / 128, MROWS / 128);
        bf3_gemm_kernel<<<grid, 256>>>((const __nv_bfloat16*)p_a3,
                                       (const __nv_bfloat16*)p_wb3,
                                       (float*)p_qkv, QKVN);
    }
    {
        int total = MROWS * (NHq + NKV) * 64;
        rope_kernel<<<(total + 255) / 256, 256>>>(positions);
    }
    {
        size_t total = (size_t)MROWS * QKVN / 4;
        splitqkv_kernel<<<(unsigned)((total + 255) / 256), 256>>>();
    }
    {
        dim3 grid(Tn / 128, NHq, Bsz);
        attn_mma_kernel<<<grid, 256, attn_smem>>>();
    }
    {
        size_t total = (size_t)MROWS * 2048;
        split3_kernel<<<(unsigned)((total + 255) / 256), 256>>>(
            (const float*)p_enc);
    }
    {
        dim3 grid(ENCN / 128, MROWS / 128);
        bf3_gemm_kernel<<<grid, 256>>>((const __nv_bfloat16*)p_a3,
                                       (const __nv_bfloat16*)p_wo3, out, ENCN);
    }
}

// round 5
// speedup vs baseline: 2.9249x; 1.0575x over previous
#include <cuda_runtime.h>
#include <cuda_bf16.h>
#include <math.h>

// Problem constants
#define Bsz 2
#define Tn 2048
#define Dm 2048
#define NHq 16
#define NKV 8
#define HD 128
#define MROWS (Bsz * Tn)          // 4096 tokens
#define QKVN 4096                 // 2048 q | 1024 k | 1024 v
#define KOFF 2048
#define VOFF 3072
#define ENCN 2048
#define K3 6144                   // 3x split-bf16 K dimension
#define BIG_NEG -2.3819763e38f

// Scratch (device globals: allocation-free per harness rules)
__device__ __nv_bfloat16 g_wb3[(size_t)K3 * QKVN];  // QKV weights, split-bf16
__device__ __nv_bfloat16 g_wo3[(size_t)K3 * ENCN];  // out weights, split-bf16
__device__ __nv_bfloat16 g_a3[(size_t)MROWS * K3];  // activations, split-bf16
__device__ float g_qkv[(size_t)MROWS * QKVN];       // QKV projections (pre-rope)
__device__ __nv_bfloat16 g_sh[(size_t)MROWS * QKVN];  // rope'd qkv hi plane
__device__ __nv_bfloat16 g_sl[(size_t)MROWS * QKVN];  // rope'd qkv lo plane

// ---------------------------------------------------------------------------
#define CPA16(dst, src) \
    asm volatile("cp.async.cg.shared.global [%0], [%1], 16;" ::"r"(dst), "l"(src))
#define LDSM4(r, addr)                                                        \
    asm volatile("ldmatrix.sync.aligned.m8n8.x4.shared.b16 {%0,%1,%2,%3},[%4];" \
                 : "=r"((r)[0]), "=r"((r)[1]), "=r"((r)[2]), "=r"((r)[3])     \
                 : "r"(addr))
#define LDSM4T(r, addr)                                                       \
    asm volatile(                                                             \
        "ldmatrix.sync.aligned.m8n8.x4.trans.shared.b16 {%0,%1,%2,%3},[%4];"  \
        : "=r"((r)[0]), "=r"((r)[1]), "=r"((r)[2]), "=r"((r)[3])              \
        : "r"(addr))
#define MMA_B16(d, a, b0, b1)                                                 \
    asm volatile(                                                             \
        "mma.sync.aligned.m16n8k16.row.col.f32.bf16.bf16.f32 "                \
        "{%0,%1,%2,%3},{%4,%5,%6,%7},{%8,%9},{%0,%1,%2,%3};"                  \
        : "+f"((d)[0]), "+f"((d)[1]), "+f"((d)[2]), "+f"((d)[3])              \
        : "r"((a)[0]), "r"((a)[1]), "r"((a)[2]), "r"((a)[3]), "r"(b0), "r"(b1))

__device__ __forceinline__ unsigned pack2bf(float a, float b) {
    __nv_bfloat162 h = __floats2bfloat162_rn(a, b);
    return *(unsigned*)&h;
}

// ---------------------------------------------------------------------------
// Pack w_q + w_kv into split-bf16 [K3=6144][4096]: row blocks [hi | lo | hi]
// ---------------------------------------------------------------------------
__global__ void pack_w3_kernel(const float* __restrict__ wq,
                               const float* __restrict__ wkv) {
    size_t idx = (size_t)blockIdx.x * blockDim.x + threadIdx.x;
    if (idx >= (size_t)K3 * QKVN) return;
    int j = (int)(idx & (QKVN - 1));
    int k3 = (int)(idx >> 12);
    int seg = k3 >> 11;
    int d = k3 & 2047;
    float w;
    if (j < KOFF) {
        int n = j >> 7, h = j & 127;
        w = wq[((size_t)n * Dm + d) * HD + h];
    } else if (j < VOFF) {
        int jj = j - KOFF;
        int n = jj >> 7, h = jj & 127;
        w = wkv[((size_t)n * Dm + d) * HD + h];
    } else {
        int jj = j - VOFF;
        int n = jj >> 7, h = jj & 127;
        w = wkv[((size_t)(NKV + n) * Dm + d) * HD + h];
    }
    __nv_bfloat16 hi = __float2bfloat16(w);
    g_wb3[idx] = (seg == 1) ? __float2bfloat16(w - __bfloat162float(hi)) : hi;
}

__global__ void pack_wo3_kernel(const float* __restrict__ wout) {
    size_t idx = (size_t)blockIdx.x * blockDim.x + threadIdx.x;
    if (idx >= (size_t)K3 * ENCN) return;
    int d = (int)(idx & (ENCN - 1));
    int k3 = (int)(idx >> 11);
    int seg = k3 >> 11;
    int kk = k3 & 2047;
    float w = wout[(size_t)kk * ENCN + d];
    __nv_bfloat16 hi = __float2bfloat16(w);
    g_wo3[idx] = (seg == 1) ? __float2bfloat16(w - __bfloat162float(hi)) : hi;
}

// Split fp32 [4096][2048] into g_a3 [4096][6144]: cols [hi|hi|lo]
__global__ void split3_kernel(const float* __restrict__ src) {
    size_t idx = (size_t)blockIdx.x * blockDim.x + threadIdx.x;
    if (idx >= (size_t)MROWS * 2048) return;
    int k = (int)(idx & 2047);
    int m = (int)(idx >> 11);
    float a = src[idx];
    __nv_bfloat16 hi = __float2bfloat16(a);
    __nv_bfloat16 lo = __float2bfloat16(a - __bfloat162float(hi));
    __nv_bfloat16* dst = g_a3 + (size_t)m * K3;
    dst[k] = hi;
    dst[k + 2048] = hi;
    dst[k + 4096] = lo;
}

// ---------------------------------------------------------------------------
// Fused RoPE + hi/lo split: reads g_qkv fp32, writes g_sh/g_sl bf16 planes.
// Each thread handles one rope pair (q/k) or two v elements.
// ---------------------------------------------------------------------------
__device__ __forceinline__ void put_hl(size_t off, float v) {
    __nv_bfloat16 hi = __float2bfloat16(v);
    g_sh[off] = hi;
    g_sl[off] = __float2bfloat16(v - __bfloat162float(hi));
}

__global__ void rope_split_kernel(const int* __restrict__ positions) {
    int idx = blockIdx.x * blockDim.x + threadIdx.x;
    if (idx >= MROWS * 2048) return;
    int p = idx & 2047;
    int m = idx >> 11;
    size_t rowOff = (size_t)m * QKVN;
    if (p < 1536) {  // q (16 heads) + k (8 heads), 64 pairs each
        int head = p >> 6, pp = p & 63;
        float t = (float)positions[m];
        float frac = (float)(2 * pp) * (1.0f / 128.0f);
        float timescale = powf(10000.0f, frac);
        float ang = t / timescale;
        float s, c;
        sincosf(ang, &s, &c);
        int col = ((head < NHq) ? head * HD : KOFF + (head - NHq) * HD) + pp;
        float scale = (head < NHq) ? 0.08838834764831845f : 1.0f;
        const float* base = g_qkv + rowOff + col;
        float x1 = base[0], x2 = base[64];
        put_hl(rowOff + col, (x1 * c - x2 * s) * scale);
        put_hl(rowOff + col + 64, (x2 * c + x1 * s) * scale);
    } else {  // v: no rope, just convert 2 elems
        int col = VOFF + (p - 1536) * 2;
        put_hl(rowOff + col, g_qkv[rowOff + col]);
        put_hl(rowOff + col + 1, g_qkv[rowOff + col + 1]);
    }
}

// ---------------------------------------------------------------------------
// Split-bf16 GEMM v2: 128x128x32 tile, 4-stage cp.async pipeline, 256 threads
// ---------------------------------------------------------------------------
#define GBM 128
#define GBK 32
#define ASTR 40
#define BSTR 136
#define NSTG 4
#define A_BY (GBM * ASTR * 2)     // 10240
#define B_BY (GBK * BSTR * 2)     // 8704
#define STG_BY (A_BY + B_BY)      // 18944

#define GEMM_ISSUE(itv)                                                       \
    {                                                                         \
        const int k0 = (itv) * GBK;                                           \
        const unsigned aOff = smBase + ((itv) % NSTG) * STG_BY;               \
        const unsigned bOff = aOff + A_BY;                                    \
        CPA16(aOff + (arow * ASTR + ach) * 2,                                 \
              A + (size_t)(rowBlock + arow) * K3 + k0 + ach);                 \
        CPA16(aOff + ((arow + 64) * ASTR + ach) * 2,                          \
              A + (size_t)(rowBlock + arow + 64) * K3 + k0 + ach);            \
        CPA16(bOff + (brow * BSTR + bch) * 2,                                 \
              B + (size_t)(k0 + brow) * N + colBlock + bch);                  \
        CPA16(bOff + ((brow + 16) * BSTR + bch) * 2,                          \
              B + (size_t)(k0 + brow + 16) * N + colBlock + bch);             \
        asm volatile("cp.async.commit_group;");                               \
    }

__global__ __launch_bounds__(256, 2) void bf3_gemm_kernel(
    const __nv_bfloat16* __restrict__ A, const __nv_bfloat16* __restrict__ B,
    float* __restrict__ C, int N) {
    extern __shared__ __align__(16) char gsm[];
    const unsigned smBase = (unsigned)__cvta_generic_to_shared(gsm);
    const int tid = threadIdx.x;
    const int lane = tid & 31, warp = tid >> 5;
    const int warpM = warp >> 1, warpN = warp & 1;
    const int rowBlock = blockIdx.y * GBM, colBlock = blockIdx.x * 128;

    const int arow = tid >> 2, ach = (tid & 3) * 8;
    const int brow = tid >> 4, bch = (tid & 15) * 8;

    const int NIT = K3 / GBK;  // 192
    // Prologue: fill NSTG-1 stages
    GEMM_ISSUE(0);
    GEMM_ISSUE(1);
    GEMM_ISSUE(2);

    float acc[2][8][4] = {};
    const int ldRow = (lane & 7) + ((lane >> 3) & 1) * 8;
    const int ldCol = (lane >> 4) * 8;

    for (int it = 0; it < NIT; it++) {
        asm volatile("cp.async.wait_group 2;" ::: "memory");
        __syncthreads();
        if (it + NSTG - 1 < NIT) GEMM_ISSUE(it + NSTG - 1);

        const unsigned aOff = smBase + (it % NSTG) * STG_BY;
        const unsigned bOff = aOff + A_BY;
#pragma unroll
        for (int ks = 0; ks < 2; ks++) {
            unsigned af[2][4];
#pragma unroll
            for (int mt = 0; mt < 2; mt++) {
                unsigned addr =
                    aOff + ((warpM * 32 + mt * 16 + ldRow) * ASTR + ks * 16 + ldCol) * 2;
                LDSM4(af[mt], addr);
            }
            unsigned bfr[8][2];
#pragma unroll
            for (int np = 0; np < 4; np++) {
                unsigned addr =
                    bOff + ((ks * 16 + ldRow) * BSTR + warpN * 64 + np * 16 + ldCol) * 2;
                asm volatile(
                    "ldmatrix.sync.aligned.m8n8.x4.trans.shared.b16 {%0,%1,%2,%3}, [%4];"
                    : "=r"(bfr[np * 2][0]), "=r"(bfr[np * 2][1]),
                      "=r"(bfr[np * 2 + 1][0]), "=r"(bfr[np * 2 + 1][1])
                    : "r"(addr));
            }
#pragma unroll
            for (int mt = 0; mt < 2; mt++)
#pragma unroll
                for (int nt = 0; nt < 8; nt++)
                    MMA_B16(acc[mt][nt], af[mt], bfr[nt][0], bfr[nt][1]);
        }
    }

    const int gid = lane >> 2, tig = lane & 3;
#pragma unroll
    for (int mt = 0; mt < 2; mt++) {
        int r0 = rowBlock + warpM * 32 + mt * 16 + gid;
#pragma unroll
        for (int nt = 0; nt < 8; nt++) {
            int c = colBlock + warpN * 64 + nt * 8 + tig * 2;
            *(float2*)&C[(size_t)r0 * N + c] =
                make_float2(acc[mt][nt][0], acc[mt][nt][1]);
            *(float2*)&C[(size_t)(r0 + 8) * N + c] =
                make_float2(acc[mt][nt][2], acc[mt][nt][3]);
        }
    }
}

// ---------------------------------------------------------------------------
// Tensor-core flash attention, split-bf16 3-term (epilogue now writes g_a3).
// ---------------------------------------------------------------------------
#define ATS 136
#define ABUF (64 * ATS)
#define ASTG (4 * ABUF)

__global__ __launch_bounds__(256, 1) void attn_mma_kernel() {
    extern __shared__ __align__(16) __nv_bfloat16 sm[];
    const int tid = threadIdx.x, lane = tid & 31, warp = tid >> 5;
    const int tq = 15 - blockIdx.x;
    const int n = blockIdx.y, b = blockIdx.z, kvh = n >> 1;
    const unsigned smBase = (unsigned)__cvta_generic_to_shared(sm);

    const int kvRow = tid >> 2;
    const int kvCh = (tid & 3) * 32;
    const int qRow = tid >> 1;
    const int qCh = (tid & 1) * 64;

    const size_t kRowBase = (size_t)(b * Tn) * QKVN + KOFF + kvh * HD;
    const size_t vRowBase = (size_t)(b * Tn) * QKVN + VOFF + kvh * HD;

    {
        size_t qsrc = (size_t)(b * Tn + tq * 128 + qRow) * QKVN + n * HD + qCh;
#pragma unroll
        for (int c = 0; c < 8; c++) {
            CPA16(smBase + (ASTG + qRow * ATS + qCh + c * 8) * 2, g_sh + qsrc + c * 8);
            CPA16(smBase + (ASTG + 2 * ABUF + qRow * ATS + qCh + c * 8) * 2,
                  g_sl + qsrc + c * 8);
        }
        size_t kr = kRowBase + (size_t)kvRow * QKVN + kvCh;
        size_t vr = vRowBase + (size_t)kvRow * QKVN + kvCh;
#pragma unroll
        for (int c = 0; c < 4; c++) {
            CPA16(smBase + (0 * ABUF + kvRow * ATS + kvCh + c * 8) * 2, g_sh + kr + c * 8);
            CPA16(smBase + (1 * ABUF + kvRow * ATS + kvCh + c * 8) * 2, g_sl + kr + c * 8);
            CPA16(smBase + (2 * ABUF + kvRow * ATS + kvCh + c * 8) * 2, g_sh + vr + c * 8);
            CPA16(smBase + (3 * ABUF + kvRow * ATS + kvCh + c * 8) * 2, g_sl + vr + c * 8);
        }
        asm volatile("cp.async.commit_group;");
    }
    asm volatile("cp.async.wait_group 0;" ::: "memory");
    __syncthreads();

    unsigned qfH[8][4], qfL[8][4];
    {
        const int aRow = lane & 15;
        const int aCol = (lane >> 4) * 8;
#pragma unroll
        for (int kc = 0; kc < 8; kc++) {
            LDSM4(qfH[kc],
                  smBase + (ASTG + (warp * 16 + aRow) * ATS + kc * 16 + aCol) * 2);
            LDSM4(qfL[kc],
                  smBase + (ASTG + 2 * ABUF + (warp * 16 + aRow) * ATS + kc * 16 + aCol) * 2);
        }
    }
    __syncthreads();

    float oacc[16][4] = {};
    float m0 = -1e30f, m1 = -1e30f, l0 = 0.f, l1 = 0.f;
    const int gid = lane >> 2, tig = lane & 3;
    const int gr0 = tq * 128 + warp * 16 + gid;

    const int bkRow = ((lane >> 4) & 1) * 8 + (lane & 7);
    const int bkCol = ((lane >> 3) & 1) * 8;
    const int vRow = ((lane >> 3) & 1) * 8 + (lane & 7);
    const int vCol = ((lane >> 4) & 1) * 8;

    const int nTiles = 2 * tq + 2;
    for (int ts = 0; ts < nTiles; ts++) {
        const int stage = ts & 1;
        const unsigned stg = smBase + stage * (ASTG * 2);
        if (ts > 0) {
            asm volatile("cp.async.wait_group 0;" ::: "memory");
            __syncthreads();
        }
        if (ts + 1 < nTiles) {
            const unsigned pst = smBase + (stage ^ 1) * (ASTG * 2);
            size_t kr = kRowBase + (size_t)((ts + 1) * 64 + kvRow) * QKVN + kvCh;
            size_t vr = vRowBase + (size_t)((ts + 1) * 64 + kvRow) * QKVN + kvCh;
#pragma unroll
            for (int c = 0; c < 4; c++) {
                CPA16(pst + (0 * ABUF + kvRow * ATS + kvCh + c * 8) * 2, g_sh + kr + c * 8);
                CPA16(pst + (1 * ABUF + kvRow * ATS + kvCh + c * 8) * 2, g_sl + kr + c * 8);
                CPA16(pst + (2 * ABUF + kvRow * ATS + kvCh + c * 8) * 2, g_sh + vr + c * 8);
                CPA16(pst + (3 * ABUF + kvRow * ATS + kvCh + c * 8) * 2, g_sl + vr + c * 8);
            }
            asm volatile("cp.async.commit_group;");
        }

        // S = softcap(Q K^T), 3-term split
        float sa[8][4] = {};
#pragma unroll
        for (int pass = 0; pass < 3; pass++) {
            const unsigned kbuf = stg + ((pass == 1) ? ABUF * 2 : 0);
#pragma unroll
            for (int kc = 0; kc < 8; kc++) {
                const unsigned (*af)[4] = (pass == 2) ? qfL : qfH;
#pragma unroll
                for (int ntp = 0; ntp < 4; ntp++) {
                    unsigned bf[4];
                    LDSM4(bf, kbuf + ((ntp * 16 + bkRow) * ATS + kc * 16 + bkCol) * 2);
                    MMA_B16(sa[2 * ntp], af[kc], bf[0], bf[1]);
                    MMA_B16(sa[2 * ntp + 1], af[kc], bf[2], bf[3]);
                }
            }
        }

        const bool needMask = (ts * 64 + 63) > (tq * 128 + warp * 16);
        float tm0 = -1e30f, tm1 = -1e30f;
#pragma unroll
        for (int nt = 0; nt < 8; nt++) {
#pragma unroll
            for (int j = 0; j < 4; j++) {
                float x = fminf(fmaxf(sa[nt][j] * 0.02f, -8.f), 8.f);
                float e = __expf(2.f * x);
                float v = 50.f * __fdividef(e - 1.f, e + 1.f);
                if (needMask) {
                    int gc = ts * 64 + nt * 8 + tig * 2 + (j & 1);
                    int gr = gr0 + ((j >= 2) ? 8 : 0);
                    if (gc > gr) v = BIG_NEG;
                }
                sa[nt][j] = v;
                if (j < 2) tm0 = fmaxf(tm0, v);
                else       tm1 = fmaxf(tm1, v);
            }
        }
        tm0 = fmaxf(tm0, __shfl_xor_sync(0xffffffff, tm0, 1));
        tm0 = fmaxf(tm0, __shfl_xor_sync(0xffffffff, tm0, 2));
        tm1 = fmaxf(tm1, __shfl_xor_sync(0xffffffff, tm1, 1));
        tm1 = fmaxf(tm1, __shfl_xor_sync(0xffffffff, tm1, 2));
        float mn0 = fmaxf(m0, tm0), mn1 = fmaxf(m1, tm1);
        float sc0 = __expf(m0 - mn0), sc1 = __expf(m1 - mn1);
        m0 = mn0; m1 = mn1;
        l0 *= sc0; l1 *= sc1;
#pragma unroll
        for (int nt = 0; nt < 8; nt++) {
            float p0 = __expf(sa[nt][0] - mn0);
            float p1 = __expf(sa[nt][1] - mn0);
            float p2 = __expf(sa[nt][2] - mn1);
            float p3 = __expf(sa[nt][3] - mn1);
            sa[nt][0] = p0; sa[nt][1] = p1; sa[nt][2] = p2; sa[nt][3] = p3;
            l0 += p0 + p1; l1 += p2 + p3;
        }
#pragma unroll
        for (int nt = 0; nt < 16; nt++) {
            oacc[nt][0] *= sc0; oacc[nt][1] *= sc0;
            oacc[nt][2] *= sc1; oacc[nt][3] *= sc1;
        }

        unsigned phf[4][4], plf[4][4];
#pragma unroll
        for (int kc = 0; kc < 4; kc++) {
            float c00 = sa[2 * kc][0], c01 = sa[2 * kc][1];
            float c02 = sa[2 * kc][2], c03 = sa[2 * kc][3];
            float c10 = sa[2 * kc + 1][0], c11 = sa[2 * kc + 1][1];
            float c12 = sa[2 * kc + 1][2], c13 = sa[2 * kc + 1][3];
            phf[kc][0] = pack2bf(c00, c01);
            phf[kc][1] = pack2bf(c02, c03);
            phf[kc][2] = pack2bf(c10, c11);
            phf[kc][3] = pack2bf(c12, c13);
#pragma unroll
            for (int r = 0; r < 4; r++) {
                __nv_bfloat162 hv = *(__nv_bfloat162*)&phf[kc][r];
                float2 hf = __bfloat1622float2(hv);
                float a0, a1;
                if (r == 0) { a0 = c00; a1 = c01; }
                else if (r == 1) { a0 = c02; a1 = c03; }
                else if (r == 2) { a0 = c10; a1 = c11; }
                else { a0 = c12; a1 = c13; }
                plf[kc][r] = pack2bf(a0 - hf.x, a1 - hf.y);
            }
        }

        // O += P V, byte offsets: Vh @ ABUF*4, Vl @ ABUF*6
#pragma unroll
        for (int pass = 0; pass < 3; pass++) {
            const unsigned vbuf = stg + ((pass == 1) ? ABUF * 6 : ABUF * 4);
#pragma unroll
            for (int kc = 0; kc < 4; kc++) {
                const unsigned (*pf)[4] = (pass == 2) ? plf : phf;
#pragma unroll
                for (int hp = 0; hp < 8; hp++) {
                    unsigned bf[4];
                    LDSM4T(bf, vbuf + ((kc * 16 + vRow) * ATS + hp * 16 + vCol) * 2);
                    MMA_B16(oacc[2 * hp], pf[kc], bf[0], bf[1]);
                    MMA_B16(oacc[2 * hp + 1], pf[kc], bf[2], bf[3]);
                }
            }
        }
        __syncthreads();
    }

    // Epilogue: normalize and write straight into g_a3 split-bf16 [hi|hi|lo]
    l0 += __shfl_xor_sync(0xffffffff, l0, 1);
    l0 += __shfl_xor_sync(0xffffffff, l0, 2);
    l1 += __shfl_xor_sync(0xffffffff, l1, 1);
    l1 += __shfl_xor_sync(0xffffffff, l1, 2);
    float inv0 = 1.f / l0, inv1 = 1.f / l1;
    const size_t row0 = (size_t)(b * Tn + tq * 128 + warp * 16 + gid);
#pragma unroll
    for (int nt = 0; nt < 16; nt++) {
        int h = n * HD + nt * 8 + tig * 2;
        float a0 = oacc[nt][0] * inv0, a1 = oacc[nt][1] * inv0;
        float b0v = oacc[nt][2] * inv1, b1v = oacc[nt][3] * inv1;
        unsigned hA = pack2bf(a0, a1);
        unsigned hB = pack2bf(b0v, b1v);
        __nv_bfloat162 hAv = *(__nv_bfloat162*)&hA;
        __nv_bfloat162 hBv = *(__nv_bfloat162*)&hB;
        float2 fA = __bfloat1622float2(hAv);
        float2 fB = __bfloat1622float2(hBv);
        unsigned lA = pack2bf(a0 - fA.x, a1 - fA.y);
        unsigned lB = pack2bf(b0v - fB.x, b1v - fB.y);
        __nv_bfloat16* r0p = g_a3 + row0 * K3 + h;
        __nv_bfloat16* r1p = g_a3 + (row0 + 8) * K3 + h;
        *(unsigned*)r0p = hA;
        *(unsigned*)(r0p + 2048) = hA;
        *(unsigned*)(r0p + 4096) = lA;
        *(unsigned*)r1p = hB;
        *(unsigned*)(r1p + 2048) = hB;
        *(unsigned*)(r1p + 4096) = lB;
    }
}

// ---------------------------------------------------------------------------
extern "C" void kernel_launch(void* const* d_in, const int* in_sizes, int n_in,
                              void* d_out, int out_size) {
    (void)in_sizes; (void)n_in; (void)out_size;
    const float* x = (const float*)d_in[0];
    const int* positions = (const int*)d_in[1];
    const float* w_q = (const float*)d_in[3];
    const float* w_kv = (const float*)d_in[4];
    const float* w_out = (const float*)d_in[5];
    float* out = (float*)d_out;

    const int attn_smem = 2 * ASTG * 2;     // bytes
    const int gemm_smem = NSTG * STG_BY;    // 75776 bytes
    cudaFuncSetAttribute(attn_mma_kernel,
                         cudaFuncAttributeMaxDynamicSharedMemorySize, attn_smem);
    cudaFuncSetAttribute(bf3_gemm_kernel,
                         cudaFuncAttributeMaxDynamicSharedMemorySize, gemm_smem);

    void *p_qkv, *p_a3, *p_wb3, *p_wo3;
    cudaGetSymbolAddress(&p_qkv, g_qkv);
    cudaGetSymbolAddress(&p_a3, g_a3);
    cudaGetSymbolAddress(&p_wb3, g_wb3);
    cudaGetSymbolAddress(&p_wo3, g_wo3);

    {
        size_t total = (size_t)K3 * QKVN;
        pack_w3_kernel<<<(unsigned)((total + 255) / 256), 256>>>(w_q, w_kv);
    }
    {
        size_t total = (size_t)K3 * ENCN;
        pack_wo3_kernel<<<(unsigned)((total + 255) / 256), 256>>>(w_out);
    }
    {
        size_t total = (size_t)MROWS * 2048;
        split3_kernel<<<(unsigned)((total + 255) / 256), 256>>>(x);
    }
    {
        dim3 grid(QKVN / 128, MROWS / 128);
        bf3_gemm_kernel<<<grid, 256, gemm_smem>>>((const __nv_bfloat16*)p_a3,
                                                  (const __nv_bfloat16*)p_wb3,
                                                  (float*)p_qkv, QKVN);
    }
    {
        int total = MROWS * 2048;
        rope_split_kernel<<<(total + 255) / 256, 256>>>(positions);
    }
    {
        dim3 grid(Tn / 128, NHq, Bsz);
        attn_mma_kernel<<<grid, 256, attn_smem>>>();
    }
    {
        dim3 grid(ENCN / 128, MROWS / 128);
        bf3_gemm_kernel<<<grid, 256, gemm_smem>>>((const __nv_bfloat16*)p_a3,
                                                  (const __nv_bfloat16*)p_wo3,
                                                  out, ENCN);
    }
}